// round 15
// baseline (speedup 1.0000x reference)
#include <cuda_runtime.h>
#include <math.h>

// SphereConv: out[2,B,F,L,M] from x[B,1,C,L,M] (complex as 2 arrays) and
// w[F,C,N,1] (complex), weights interp N=64->L=256, channel-mean, sqrt(1+l)
// scale, relu on real part.
//
// R14: depth-2 register prefetch pipeline (3 rotating buffers, barrier-free).
// R6's depth-1 lookahead covered only ~1 iteration (~160-300cyc) of the
// ~380-600cyc DRAM latency; R4's smem pipeline was killed by per-stage block
// barriers. This version issues pair k+2's 4x LDG.128 while computing pair k:
// ~2 iterations of coverage >= latency. Keep evict_last loads + .cs stores.
namespace {

constexpr int B = 4, C = 32, L = 256, M = 256, F = 8, N = 64;
constexpr int FG = 2;                // f-groups per block
constexpr int FPT = F / FG;          // filters per thread = 4
constexpr int THREADS = 64 * FG;     // 128
constexpr int CSTRIDE4 = L * M / 4;  // float4 stride between channels
constexpr int NPAIR = C / 2;         // 16 channel-pairs

__device__ __forceinline__ unsigned long long mk_persist_policy()
{
    unsigned long long pol;
    asm("createpolicy.fractional.L2::evict_last.b64 %0, 1.0;" : "=l"(pol));
    return pol;
}

__device__ __forceinline__ float4 ldg_persist(const float4* p,
                                              unsigned long long pol)
{
    float4 v;
    asm("ld.global.nc.L2::cache_hint.v4.f32 {%0,%1,%2,%3}, [%4], %5;"
        : "=f"(v.x), "=f"(v.y), "=f"(v.z), "=f"(v.w)
        : "l"(p), "l"(pol));
    return v;
}

__device__ __forceinline__ void stg_stream(float4* p, float4 v)
{
    asm volatile("st.global.cs.v4.f32 [%0], {%1,%2,%3,%4};"
                 :: "l"(p), "f"(v.x), "f"(v.y), "f"(v.z), "f"(v.w)
                 : "memory");
}

__device__ __forceinline__ void cplx_fma(float4& arf, float4& aif,
                                         float a, float bb,
                                         const float4& vr, const float4& vi)
{
    arf.x = fmaf(a, vr.x, fmaf(-bb, vi.x, arf.x));
    arf.y = fmaf(a, vr.y, fmaf(-bb, vi.y, arf.y));
    arf.z = fmaf(a, vr.z, fmaf(-bb, vi.z, arf.z));
    arf.w = fmaf(a, vr.w, fmaf(-bb, vi.w, arf.w));
    aif.x = fmaf(a, vi.x, fmaf( bb, vr.x, aif.x));
    aif.y = fmaf(a, vi.y, fmaf( bb, vr.y, aif.y));
    aif.z = fmaf(a, vi.z, fmaf( bb, vr.z, aif.z));
    aif.w = fmaf(a, vi.w, fmaf( bb, vr.w, aif.w));
}

struct PairBuf {
    float4 vr0, vi0, vr1, vi1;
};

__device__ __forceinline__ void load_pair(PairBuf& pb, const float4* xr4,
                                          const float4* xi4, int c,
                                          unsigned long long pol)
{
    pb.vr0 = ldg_persist(xr4 + c * CSTRIDE4, pol);
    pb.vi0 = ldg_persist(xi4 + c * CSTRIDE4, pol);
    pb.vr1 = ldg_persist(xr4 + (c + 1) * CSTRIDE4, pol);
    pb.vi1 = ldg_persist(xi4 + (c + 1) * CSTRIDE4, pol);
}

__global__ __launch_bounds__(THREADS, 5)
void sphere_conv_kernel(const float* __restrict__ xr,
                        const float* __restrict__ xi,
                        const float* __restrict__ wr,
                        const float* __restrict__ wi,
                        float* __restrict__ out)
{
    const int bl = blockIdx.x;
    const int b  = bl >> 8;        // bl / L
    const int l  = bl & (L - 1);   // bl % L

    // Interpolated weights for this l, laid out [c][f] so 4 f's load as float4.
    __shared__ float swr[C * F];
    __shared__ float swi[C * F];

    const int tid = threadIdx.x;
    const int fg  = tid >> 6;      // f-group (0/1)
    const int m4  = tid & 63;      // float4 index within the M=256 row

    {
        float t  = ((float)l / (float)(L - 1)) * (float)(N - 1);
        int   lo = (int)floorf(t);
        lo = lo < 0 ? 0 : (lo > N - 2 ? N - 2 : lo);
        float frac = t - (float)lo;
        float sc = sqrtf(1.0f + (float)l) * (1.0f / (float)C);
        for (int i = tid; i < C * F; i += THREADS) {
            int c = i >> 3;   // i / F
            int f = i & 7;    // i % F
            int widx = (f * C + c) * N + lo;
            swr[i] = (wr[widx] * (1.0f - frac) + wr[widx + 1] * frac) * sc;
            swi[i] = (wi[widx] * (1.0f - frac) + wi[widx + 1] * frac) * sc;
        }
    }
    __syncthreads();

    const unsigned long long pol = mk_persist_policy();

    const size_t base4 = ((size_t)b * C * L + l) * (M / 4) + m4;
    const float4* xr4 = reinterpret_cast<const float4*>(xr) + base4;
    const float4* xi4 = reinterpret_cast<const float4*>(xi) + base4;

    float4 ar[FPT], ai[FPT];
#pragma unroll
    for (int f = 0; f < FPT; ++f) {
        ar[f] = make_float4(0.f, 0.f, 0.f, 0.f);
        ai[f] = make_float4(0.f, 0.f, 0.f, 0.f);
    }

    const float4* swr4 = reinterpret_cast<const float4*>(swr) + fg;
    const float4* swi4 = reinterpret_cast<const float4*>(swi) + fg;

    // Depth-2 pipeline: 3 rotating pair buffers.
    PairBuf buf[3];
    load_pair(buf[0], xr4, xi4, 0, pol);
    load_pair(buf[1], xr4, xi4, 2, pol);

#pragma unroll
    for (int k = 0; k < NPAIR; ++k) {
        if (k + 2 < NPAIR)
            load_pair(buf[(k + 2) % 3], xr4, xi4, (k + 2) * 2, pol);

        const PairBuf& pb = buf[k % 3];
        const int c0 = k * 2;
        {
            float4 w0 = swr4[c0 * 2];
            float4 u0 = swi4[c0 * 2];
            float wv[4] = {w0.x, w0.y, w0.z, w0.w};
            float uv[4] = {u0.x, u0.y, u0.z, u0.w};
#pragma unroll
            for (int f = 0; f < FPT; ++f)
                cplx_fma(ar[f], ai[f], wv[f], uv[f], pb.vr0, pb.vi0);
        }
        {
            float4 w0 = swr4[(c0 + 1) * 2];
            float4 u0 = swi4[(c0 + 1) * 2];
            float wv[4] = {w0.x, w0.y, w0.z, w0.w};
            float uv[4] = {u0.x, u0.y, u0.z, u0.w};
#pragma unroll
            for (int f = 0; f < FPT; ++f)
                cplx_fma(ar[f], ai[f], wv[f], uv[f], pb.vr1, pb.vi1);
        }
    }

    // out shape (2, B, F, L, M); relu on real part; streaming stores.
    float4* out4 = reinterpret_cast<float4*>(out);
#pragma unroll
    for (int f = 0; f < FPT; ++f) {
        int fglob = fg * FPT + f;
        float4 r = ar[f];
        r.x = fmaxf(r.x, 0.f);
        r.y = fmaxf(r.y, 0.f);
        r.z = fmaxf(r.z, 0.f);
        r.w = fmaxf(r.w, 0.f);
        size_t or4 = (((size_t)(0 * B + b) * F + fglob) * L + l) * (M / 4) + m4;
        size_t oi4 = (((size_t)(1 * B + b) * F + fglob) * L + l) * (M / 4) + m4;
        stg_stream(out4 + or4, r);
        stg_stream(out4 + oi4, ai[f]);
    }
}

}  // namespace

extern "C" void kernel_launch(void* const* d_in, const int* in_sizes, int n_in,
                              void* d_out, int out_size)
{
    const float* xr = (const float*)d_in[0];
    const float* xi = (const float*)d_in[1];
    const float* wr = (const float*)d_in[2];
    const float* wi = (const float*)d_in[3];
    float* out = (float*)d_out;
    sphere_conv_kernel<<<B * L, THREADS>>>(xr, xi, wr, wi, out);
}